// round 8
// baseline (speedup 1.0000x reference)
#include <cuda_runtime.h>

// Problem constants (fixed by the reference: T=512 steps, B=64, E=512)
#define T_STEPS 512
#define B_SZ    64
#define E_SZ    512
#define MAXW    64     // max slots overlapping a width-1 read window
#define TB_T    4      // t-tiles per block in the read kernel
#define SPAN_CHUNK 128 // rows of dense coeffs staged per pass

// Scratch (static __device__ -- no allocations)
__device__ int   g_meta[B_SZ][T_STEPS];           // lo | (cnt<<16)
__device__ float g_c   [B_SZ][T_STEPS][MAXW];

// ---------------------------------------------------------------------------
// float-float (double-float) arithmetic: ~47-bit precision, all on FMA pipe.
// ---------------------------------------------------------------------------
struct ff { float h, l; };

__device__ __forceinline__ ff ff_norm(float s, float e) {
    float h = s + e;
    return { h, e - (h - s) };
}
__device__ __forceinline__ ff ff_add(ff a, ff b) {
    float s = a.h + b.h;
    float v = s - a.h;
    float e = (a.h - (s - v)) + (b.h - v);          // exact TwoSum error
    return ff_norm(s, e + a.l + b.l);
}
__device__ __forceinline__ ff ff_neg(ff a) { return { -a.h, -a.l }; }
__device__ __forceinline__ bool ff_gt(ff a, ff b) {
    return (a.h > b.h) || (a.h == b.h && a.l > b.l);
}
__device__ __forceinline__ bool ff_lt(ff a, ff b) { return ff_gt(b, a); }

// mask MUST name exactly the converged lanes at the call site.
__device__ __forceinline__ ff ff_shfl_up(unsigned mask, ff a, int o) {
    ff r;
    r.h = __shfl_up_sync(mask, a.h, o);
    r.l = __shfl_up_sync(mask, a.l, o);
    return r;
}

// ---------------------------------------------------------------------------
// Kernel 1: per-batch queue recurrence via tape model (float-float precision).
//   A_i   = inclusive cumsum of d
//   SU_t  = inclusive cumsum of u
//   pop_t = SU_t + min_{j<=t}(A_{j-1} - SU_j)
//   c_i^t = max(0, min(A_i, pop_t+1) - max(A_{i-1}, pop_t))
// ---------------------------------------------------------------------------
__global__ void __launch_bounds__(T_STEPS) queue_coeffs(const float* __restrict__ U,
                                                        const float* __restrict__ D)
{
    const int b    = blockIdx.x;
    const int t    = threadIdx.x;
    const int lane = t & 31;
    const int wid  = t >> 5;            // 16 warps

    __shared__ float sAh[T_STEPS];
    __shared__ float sAl[T_STEPS];
    __shared__ ff    swD[16], swU[16], swM[16];

    ff x  = { D[t * B_SZ + b], 0.f };
    ff su = { U[t * B_SZ + b], 0.f };

    // ---- inclusive warp scans of d and u (full warp converged) ----
    #pragma unroll
    for (int o = 1; o < 32; o <<= 1) {
        ff y0 = ff_shfl_up(0xffffffffu, x, o);
        ff y1 = ff_shfl_up(0xffffffffu, su, o);
        if (lane >= o) { x = ff_add(x, y0); su = ff_add(su, y1); }
    }
    if (lane == 31) { swD[wid] = x; swU[wid] = su; }
    __syncthreads();
    if (t < 16) {   // only lanes 0-15 of warp 0 converge here
        ff y0 = swD[t], y1 = swU[t];
        #pragma unroll
        for (int o = 1; o < 16; o <<= 1) {
            ff z0 = ff_shfl_up(0x0000ffffu, y0, o);
            ff z1 = ff_shfl_up(0x0000ffffu, y1, o);
            if (lane >= o) { y0 = ff_add(y0, z0); y1 = ff_add(y1, z1); }
        }
        swD[t] = y0; swU[t] = y1;
    }
    __syncthreads();
    ff A  = wid ? ff_add(x,  swD[wid - 1]) : x;     // inclusive cumsum D
    ff SU = wid ? ff_add(su, swU[wid - 1]) : su;    // inclusive cumsum U
    sAh[t] = A.h; sAl[t] = A.l;
    __syncthreads();

    // ---- prefix-min of g_t = A_{t-1} - SU_t  ->  pop_t ----
    ff Aprev = t ? ff{ sAh[t - 1], sAl[t - 1] } : ff{ 0.f, 0.f };
    ff m = ff_add(Aprev, ff_neg(SU));
    #pragma unroll
    for (int o = 1; o < 32; o <<= 1) {
        ff y = ff_shfl_up(0xffffffffu, m, o);
        if (lane >= o && ff_lt(y, m)) m = y;
    }
    if (lane == 31) swM[wid] = m;
    __syncthreads();
    if (t < 16) {
        ff y = swM[t];
        #pragma unroll
        for (int o = 1; o < 16; o <<= 1) {
            ff z = ff_shfl_up(0x0000ffffu, y, o);
            if (lane >= o && ff_lt(z, y)) y = z;
        }
        swM[t] = y;
    }
    __syncthreads();
    if (wid && ff_lt(swM[wid - 1], m)) m = swM[wid - 1];
    const ff pop = ff_add(SU, m);

    // ---- window extraction: first slot i in [0, t] with A_i > pop ----
    int loI = 0, hiI = t + 1;
    while (loI < hiI) {
        int mid = (loI + hiI) >> 1;
        ff Am = { sAh[mid], sAl[mid] };
        if (ff_gt(Am, pop)) hiI = mid; else loI = mid + 1;
    }

    const ff lim = ff_add(pop, ff{ 1.f, 0.f });
    ff prev = loI ? ff{ sAh[loI - 1], sAl[loI - 1] } : ff{ 0.f, 0.f };
    int cnt = 0;
    int i = loI;
    while (i <= t && ff_lt(prev, lim) && cnt < MAXW) {
        ff Ai  = { sAh[i], sAl[i] };
        ff top = ff_lt(Ai, lim)   ? Ai   : lim;
        ff bot = ff_gt(prev, pop) ? prev : pop;
        float c = ff_add(top, ff_neg(bot)).h;
        g_c[b][t][cnt] = fmaxf(c, 0.f);
        cnt++;
        prev = Ai;
        i++;
    }
    g_meta[b][t] = loI | (cnt << 16);
}

// ---------------------------------------------------------------------------
// Kernel 2: r_t[b,:] = sum_{i in window} c_i * V[i,b,:]
// One block per (b, 4 consecutive t). 128 threads x float4 covers E=512.
// A dense coefficient tile sc2[row][4] is staged in smem once per block, so
// the inner loop is just: 1x LDS.128 (warp-broadcast) + 1x LDG.128 + 16 FFMA
// per row -- no per-(row,k) window tests in the hot loop.
// ---------------------------------------------------------------------------
__global__ void __launch_bounds__(128) queue_read(const float* __restrict__ V,
                                                  float* __restrict__ out)
{
    const int b    = blockIdx.x;
    const int t0   = blockIdx.y * TB_T;
    const int tid  = threadIdx.x;

    __shared__ int   smeta[TB_T];
    __shared__ float sc2[SPAN_CHUNK][TB_T];   // dense coeffs, float4 per row

    if (tid < TB_T) smeta[tid] = g_meta[b][t0 + tid];
    __syncthreads();

    int rlo[TB_T], rcnt[TB_T];
    int lomin = 0x7fffffff, himax = 0;
    #pragma unroll
    for (int k = 0; k < TB_T; k++) {
        int mt  = smeta[k];
        rlo[k]  = mt & 0xffff;
        rcnt[k] = mt >> 16;
        if (rcnt[k] > 0) {
            lomin = min(lomin, rlo[k]);
            himax = max(himax, rlo[k] + rcnt[k]);
        }
    }

    float4 acc[TB_T];
    #pragma unroll
    for (int k = 0; k < TB_T; k++) acc[k] = make_float4(0.f, 0.f, 0.f, 0.f);

    const size_t STRIDE = (size_t)B_SZ * (E_SZ / 4);      // float4s per s step
    const float4* __restrict__ Vbase =
        (const float4*)V + (size_t)b * (E_SZ / 4) + tid;

    // chunked over the window union (one pass in practice: span ~6 rows)
    for (int base = lomin; base < himax; base += SPAN_CHUNK) {
        const int chunk = min(himax - base, SPAN_CHUNK);

        // ---- stage dense coefficient tile ----
        for (int idx = tid; idx < chunk * TB_T; idx += 128) {
            const int j = idx >> 2;
            const int k = idx & 3;
            const unsigned rel = (unsigned)(base + j - rlo[k]);
            float c = 0.f;
            if (rel < (unsigned)rcnt[k]) c = g_c[b][t0 + k][rel];
            sc2[j][k] = c;
        }
        __syncthreads();

        // ---- hot loop: unroll-by-2 rows ----
        const float4* p = Vbase + (size_t)base * STRIDE;
        for (int j = 0; j < chunk; j += 2) {
            const int jc = min(j + 1, chunk - 1);
            float4 va = p[(size_t)j  * STRIDE];
            float4 vb = p[(size_t)jc * STRIDE];
            float4 ca = *(const float4*)sc2[j];
            float4 cb = *(const float4*)sc2[jc];
            if (j + 1 >= chunk) cb = make_float4(0.f, 0.f, 0.f, 0.f);  // tail guard

            acc[0].x += ca.x * va.x;  acc[0].y += ca.x * va.y;
            acc[0].z += ca.x * va.z;  acc[0].w += ca.x * va.w;
            acc[1].x += ca.y * va.x;  acc[1].y += ca.y * va.y;
            acc[1].z += ca.y * va.z;  acc[1].w += ca.y * va.w;
            acc[2].x += ca.z * va.x;  acc[2].y += ca.z * va.y;
            acc[2].z += ca.z * va.z;  acc[2].w += ca.z * va.w;
            acc[3].x += ca.w * va.x;  acc[3].y += ca.w * va.y;
            acc[3].z += ca.w * va.z;  acc[3].w += ca.w * va.w;

            acc[0].x += cb.x * vb.x;  acc[0].y += cb.x * vb.y;
            acc[0].z += cb.x * vb.z;  acc[0].w += cb.x * vb.w;
            acc[1].x += cb.y * vb.x;  acc[1].y += cb.y * vb.y;
            acc[1].z += cb.y * vb.z;  acc[1].w += cb.y * vb.w;
            acc[2].x += cb.z * vb.x;  acc[2].y += cb.z * vb.y;
            acc[2].z += cb.z * vb.z;  acc[2].w += cb.z * vb.w;
            acc[3].x += cb.w * vb.x;  acc[3].y += cb.w * vb.y;
            acc[3].z += cb.w * vb.z;  acc[3].w += cb.w * vb.w;
        }
        __syncthreads();   // protect sc2 before next chunk's restage
    }

    #pragma unroll
    for (int k = 0; k < TB_T; k++) {
        float4* dst = (float4*)out + (size_t)((t0 + k) * B_SZ + b) * (E_SZ / 4) + tid;
        __stcs(dst, acc[k]);   // streaming store: keep V resident in L2
    }
}

// ---------------------------------------------------------------------------
extern "C" void kernel_launch(void* const* d_in, const int* in_sizes, int n_in,
                              void* d_out, int out_size)
{
    const float* V = (const float*)d_in[0];   // [T, B, E]
    const float* U = (const float*)d_in[1];   // [T, B]
    const float* D = (const float*)d_in[2];   // [T, B]
    float* out = (float*)d_out;               // [T, B, E]

    queue_coeffs<<<B_SZ, T_STEPS>>>(U, D);

    dim3 grid(B_SZ, T_STEPS / TB_T);
    queue_read<<<grid, 128>>>(V, out);
}